// round 2
// baseline (speedup 1.0000x reference)
#include <cuda_runtime.h>
#include <cuda_bf16.h>
#include <cstdint>

#define BB 32
#define LL 512
#define DD 256
#define FF 256
#define TL 16   // L positions per conv block

// Scratch (allocation-free rule): h1 = post-conv1/LN/ReLU activations
__device__ float g_h1[BB * LL * FF];
__device__ int   g_cs[BB * LL];

// ---------------------------------------------------------------------------
// Kernel 1: per-batch inclusive cumsum of durations (L=512)
// ---------------------------------------------------------------------------
__global__ void cumsum_kernel(const int* __restrict__ dur) {
    __shared__ int s[LL];
    int t = threadIdx.x;
    int b = blockIdx.x;
    s[t] = dur[b * LL + t];
    for (int off = 1; off < LL; off <<= 1) {
        __syncthreads();
        int v = (t >= off) ? s[t - off] : 0;
        __syncthreads();
        s[t] += v;
    }
    g_cs[b * LL + t] = s[t];
}

// ---------------------------------------------------------------------------
// Kernel 2: expand — one warp per output frame, binary search + float4 copy
// ---------------------------------------------------------------------------
__global__ void expand_kernel(const float* __restrict__ x,
                              float* __restrict__ out, int M) {
    __shared__ int cs[LL];
    int b = blockIdx.y;
    for (int i = threadIdx.x; i < LL; i += blockDim.x)
        cs[i] = g_cs[b * LL + i];
    __syncthreads();

    int warp = threadIdx.x >> 5;
    int lane = threadIdx.x & 31;
    int frame = blockIdx.x * 8 + warp;
    if (frame >= M) return;

    int total = cs[LL - 1];
    int lo = 0, hi = LL;
    while (lo < hi) {
        int mid = (lo + hi) >> 1;
        if (cs[mid] > frame) hi = mid; else lo = mid + 1;
    }
    int idx = lo < (LL - 1) ? lo : (LL - 1);
    bool valid = frame < total;

    const float4* src = reinterpret_cast<const float4*>(x + ((size_t)b * LL + idx) * DD);
    float4* dst = reinterpret_cast<float4*>(out + ((size_t)b * M + frame) * DD);
    float4 z = make_float4(0.f, 0.f, 0.f, 0.f);
    dst[lane]      = valid ? src[lane]      : z;
    dst[lane + 32] = valid ? src[lane + 32] : z;
}

// ---------------------------------------------------------------------------
// Packed f32x2 helpers (Blackwell sm_103a FFMA2 path)
// ---------------------------------------------------------------------------
__device__ __forceinline__ void ffma2(uint64_t& acc, uint64_t a, uint64_t b) {
    asm("fma.rn.f32x2 %0, %1, %2, %0;" : "+l"(acc) : "l"(a), "l"(b));
}
__device__ __forceinline__ uint64_t pack2(float lo, float hi) {
    uint64_t r;
    asm("mov.b64 %0, {%1, %2};" : "=l"(r) : "f"(lo), "f"(hi));
    return r;
}
__device__ __forceinline__ float pairsum(uint64_t p) {
    float lo, hi;
    asm("mov.b64 {%0, %1}, %2;" : "=f"(lo), "=f"(hi) : "l"(p));
    return lo + hi;
}

// ---------------------------------------------------------------------------
// Kernel 3/4: conv1d(K=3, same-pad) + LayerNorm + ReLU, optionally fused
// linear head. Accumulators are f32x2 pairs over input-channel parity:
// lane0 = even-d partial sum, lane1 = odd-d partial sum, merged at the end.
// grid: (L/TL, B), block 256 (thread = output channel f)
// ---------------------------------------------------------------------------
template <bool FUSE_LIN>
__global__ void __launch_bounds__(256)
conv_ln_kernel(const float* __restrict__ in,     // [B, L, 256]
               const float* __restrict__ w,      // [3, 256, 256]
               const float* __restrict__ bias,   // [256]
               const float* __restrict__ lng,    // [256]
               const float* __restrict__ lnb,    // [256]
               const float* __restrict__ lw,     // [256]
               const float* __restrict__ lb,     // [1]
               float* __restrict__ out)          // h1 [B,L,256] or dur_pred [B,L]
{
    __shared__ float xs[(TL + 2) * DD];   // 18 KB input halo tile
    __shared__ float wsum[TL][8], wsq[TL][8];
    __shared__ float stats[TL][2];        // mu, rstd per position

    const int f  = threadIdx.x;
    const int b  = blockIdx.y;
    const int l0 = blockIdx.x * TL;
    const int lane = f & 31;
    const int wrp  = f >> 5;

    // Load (TL+2) input rows with zero padding at sequence edges
    #pragma unroll
    for (int i = 0; i < TL + 2; i++) {
        int l = l0 - 1 + i;
        xs[i * DD + f] = (l >= 0 && l < LL) ? in[((size_t)b * LL + l) * DD + f] : 0.f;
    }
    __syncthreads();

    uint64_t acc2[TL];
    const uint64_t zero2 = 0ull;  // {0.f, 0.f}
    #pragma unroll
    for (int l = 0; l < TL; l++) acc2[l] = zero2;

    // Main loop: 2 input channels per iteration, f32x2 packed FMAs
    for (int d = 0; d < DD; d += 2) {
        uint64_t xp[TL + 2];
        #pragma unroll
        for (int i = 0; i < TL + 2; i++)
            xp[i] = *reinterpret_cast<const uint64_t*>(&xs[i * DD + d]);  // LDS.64 broadcast

        uint64_t wp[3];
        #pragma unroll
        for (int k = 0; k < 3; k++) {
            float w0 = w[((size_t)(k * DD + d    )) * FF + f];   // coalesced LDG
            float w1 = w[((size_t)(k * DD + d + 1)) * FF + f];
            wp[k] = pack2(w0, w1);
        }
        #pragma unroll
        for (int k = 0; k < 3; k++)
            #pragma unroll
            for (int l = 0; l < TL; l++)
                ffma2(acc2[l], xp[l + k], wp[k]);
    }

    // Merge pair lanes + bias
    const float bi = bias[f];
    float v[TL];
    #pragma unroll
    for (int l = 0; l < TL; l++) v[l] = pairsum(acc2[l]) + bi;

    // --- LayerNorm stats: two-level reduction, only 2 barriers ---
    #pragma unroll
    for (int l = 0; l < TL; l++) {
        float s = v[l], q = v[l] * v[l];
        #pragma unroll
        for (int o = 16; o; o >>= 1) {
            s += __shfl_xor_sync(0xFFFFFFFFu, s, o);
            q += __shfl_xor_sync(0xFFFFFFFFu, q, o);
        }
        if (lane == 0) { wsum[l][wrp] = s; wsq[l][wrp] = q; }
    }
    __syncthreads();
    if (f < TL) {
        float S = 0.f, Q = 0.f;
        #pragma unroll
        for (int j = 0; j < 8; j++) { S += wsum[f][j]; Q += wsq[f][j]; }
        float mu  = S * (1.f / FF);
        float var = Q * (1.f / FF) - mu * mu;
        stats[f][0] = mu;
        stats[f][1] = rsqrtf(var + 1e-5f);
    }
    __syncthreads();

    const float gf = lng[f];
    const float bf = lnb[f];

    if (!FUSE_LIN) {
        #pragma unroll
        for (int l = 0; l < TL; l++) {
            float h = fmaxf((v[l] - stats[l][0]) * stats[l][1] * gf + bf, 0.f);
            out[((size_t)b * LL + l0 + l) * FF + f] = h;
        }
    } else {
        const float lwf = lw[f];
        const float lbv = lb[0];
        #pragma unroll
        for (int l = 0; l < TL; l++) {
            float h = fmaxf((v[l] - stats[l][0]) * stats[l][1] * gf + bf, 0.f);
            float p = h * lwf;
            #pragma unroll
            for (int o = 16; o; o >>= 1)
                p += __shfl_xor_sync(0xFFFFFFFFu, p, o);
            if (lane == 0) wsum[l][wrp] = p;   // reuse wsum staging
        }
        __syncthreads();
        if (f < TL) {
            float S = 0.f;
            #pragma unroll
            for (int j = 0; j < 8; j++) S += wsum[f][j];
            out[(size_t)b * LL + l0 + f] = fmaxf(S + lbv, 0.f);
        }
    }
}

// ---------------------------------------------------------------------------
extern "C" void kernel_launch(void* const* d_in, const int* in_sizes, int n_in,
                              void* d_out, int out_size) {
    const float* x    = (const float*)d_in[0];
    const int*   dur  = (const int*)  d_in[1];
    const float* c1w  = (const float*)d_in[3];
    const float* c1b  = (const float*)d_in[4];
    const float* ln1g = (const float*)d_in[5];
    const float* ln1b = (const float*)d_in[6];
    const float* c2w  = (const float*)d_in[7];
    const float* c2b  = (const float*)d_in[8];
    const float* ln2g = (const float*)d_in[9];
    const float* ln2b = (const float*)d_in[10];
    const float* lw   = (const float*)d_in[11];
    const float* lb   = (const float*)d_in[12];

    float* out = (float*)d_out;
    int M = (out_size - BB * LL) / (BB * DD);        // = 4096
    float* dur_pred = out + (size_t)BB * M * DD;

    float* h1;
    cudaGetSymbolAddress((void**)&h1, g_h1);

    // Expand path
    cumsum_kernel<<<BB, LL>>>(dur);
    expand_kernel<<<dim3((M + 7) / 8, BB), 256>>>(x, out, M);

    // Duration predictor path
    conv_ln_kernel<false><<<dim3(LL / TL, BB), 256>>>(
        x, c1w, c1b, ln1g, ln1b, nullptr, nullptr, h1);
    conv_ln_kernel<true><<<dim3(LL / TL, BB), 256>>>(
        h1, c2w, c2b, ln2g, ln2b, lw, lb, dur_pred);
}

// round 3
// speedup vs baseline: 1.2575x; 1.2575x over previous
#include <cuda_runtime.h>
#include <cuda_bf16.h>
#include <cstdint>

#define BB 32
#define LL 512
#define DD 256
#define FF 256
#define TL 16      // L positions per conv block
#define NP 8       // position pairs per thread
#define SPITCH 20  // transposed smem pitch (18 positions + pad, 8B-aligned pairs)

__device__ float g_h1[BB * LL * FF];
__device__ int   g_cs[BB * LL];

// ---------------------------------------------------------------------------
// Kernel 1: per-batch inclusive cumsum of durations (L=512)
// ---------------------------------------------------------------------------
__global__ void cumsum_kernel(const int* __restrict__ dur) {
    __shared__ int s[LL];
    int t = threadIdx.x;
    int b = blockIdx.x;
    s[t] = dur[b * LL + t];
    for (int off = 1; off < LL; off <<= 1) {
        __syncthreads();
        int v = (t >= off) ? s[t - off] : 0;
        __syncthreads();
        s[t] += v;
    }
    g_cs[b * LL + t] = s[t];
}

// ---------------------------------------------------------------------------
// Kernel 2: expand — one warp per output frame, binary search + float4 copy
// ---------------------------------------------------------------------------
__global__ void expand_kernel(const float* __restrict__ x,
                              float* __restrict__ out, int M) {
    __shared__ int cs[LL];
    int b = blockIdx.y;
    for (int i = threadIdx.x; i < LL; i += blockDim.x)
        cs[i] = g_cs[b * LL + i];
    __syncthreads();

    int warp = threadIdx.x >> 5;
    int lane = threadIdx.x & 31;
    int frame = blockIdx.x * 8 + warp;
    if (frame >= M) return;

    int total = cs[LL - 1];
    int lo = 0, hi = LL;
    while (lo < hi) {
        int mid = (lo + hi) >> 1;
        if (cs[mid] > frame) hi = mid; else lo = mid + 1;
    }
    int idx = lo < (LL - 1) ? lo : (LL - 1);
    bool valid = frame < total;

    const float4* src = reinterpret_cast<const float4*>(x + ((size_t)b * LL + idx) * DD);
    float4* dst = reinterpret_cast<float4*>(out + ((size_t)b * M + frame) * DD);
    float4 z = make_float4(0.f, 0.f, 0.f, 0.f);
    dst[lane]      = valid ? src[lane]      : z;
    dst[lane + 32] = valid ? src[lane + 32] : z;
}

// ---------------------------------------------------------------------------
// Packed f32x2 helpers (Blackwell FFMA2)
// ---------------------------------------------------------------------------
__device__ __forceinline__ void ffma2(uint64_t& acc, uint64_t a, uint64_t b) {
    asm("fma.rn.f32x2 %0, %1, %2, %0;" : "+l"(acc) : "l"(a), "l"(b));
}
__device__ __forceinline__ uint64_t pack2(float lo, float hi) {
    uint64_t r;
    asm("mov.b64 %0, {%1, %2};" : "=l"(r) : "f"(lo), "f"(hi));
    return r;
}
__device__ __forceinline__ void unpack2(uint64_t p, float& lo, float& hi) {
    asm("mov.b64 {%0, %1}, %2;" : "=f"(lo), "=f"(hi) : "l"(p));
}

// ---------------------------------------------------------------------------
// Kernel 3/4: conv1d(K=3) + LayerNorm + ReLU (+ optional fused linear head).
// f32x2 accumulators paired over POSITIONS: acc2[j] = positions {2j, 2j+1}.
// Input tile kept transposed in smem so position pairs are contiguous LDS.64.
// grid: (L/TL, B), block 256 (thread = output channel f)
// ---------------------------------------------------------------------------
template <bool FUSE_LIN>
__global__ void __launch_bounds__(256)
conv_ln_kernel(const float* __restrict__ in,     // [B, L, 256]
               const float* __restrict__ w,      // [3, 256, 256]
               const float* __restrict__ bias,   // [256]
               const float* __restrict__ lng,    // [256]
               const float* __restrict__ lnb,    // [256]
               const float* __restrict__ lw,     // [256]
               const float* __restrict__ lb,     // [1]
               float* __restrict__ out)          // h1 [B,L,256] or dur_pred [B,L]
{
    __shared__ float xs_t[DD * SPITCH];   // transposed tile [channel][position], 20 KB
    __shared__ float wsum[TL][8], wsq[TL][8];
    __shared__ float stats[TL][2];

    const int f  = threadIdx.x;
    const int b  = blockIdx.y;
    const int l0 = blockIdx.x * TL;
    const int lane = f & 31;
    const int wrp  = f >> 5;

    // Load (TL+2) positions of channel f, transposed, zero-padded at edges
    #pragma unroll
    for (int i = 0; i < TL + 2; i++) {
        int l = l0 - 1 + i;
        xs_t[f * SPITCH + i] =
            (l >= 0 && l < LL) ? in[((size_t)b * LL + l) * DD + f] : 0.f;
    }
    __syncthreads();

    uint64_t acc2[NP];
    #pragma unroll
    for (int j = 0; j < NP; j++) acc2[j] = 0ull;

    #pragma unroll 2
    for (int d = 0; d < DD; d++) {
        const float* xrow = &xs_t[d * SPITCH];
        // 9 aligned LDS.64: position pairs starting at 0,2,...,16
        uint64_t xe[NP + 1];
        #pragma unroll
        for (int j = 0; j <= NP; j++)
            xe[j] = *reinterpret_cast<const uint64_t*>(&xrow[2 * j]);

        uint64_t wq[3];
        #pragma unroll
        for (int k = 0; k < 3; k++) {
            float wv = w[((size_t)(k * DD + d)) * FF + f];  // coalesced
            wq[k] = pack2(wv, wv);
        }

        #pragma unroll
        for (int j = 0; j < NP; j++) {
            float e_hi, e_lo_next, dummy0, dummy1;
            unpack2(xe[j], dummy0, e_hi);          // hi of pair j
            unpack2(xe[j + 1], e_lo_next, dummy1); // lo of pair j+1
            uint64_t xo = pack2(e_hi, e_lo_next);  // odd-start pair
            ffma2(acc2[j], xe[j],     wq[0]);
            ffma2(acc2[j], xo,        wq[1]);
            ffma2(acc2[j], xe[j + 1], wq[2]);
        }
    }

    // Unpack accumulators + bias
    const float bi = bias[f];
    float v[TL];
    #pragma unroll
    for (int j = 0; j < NP; j++) {
        float a, c;
        unpack2(acc2[j], a, c);
        v[2 * j]     = a + bi;
        v[2 * j + 1] = c + bi;
    }

    // LayerNorm stats: two-level reduction, 2 barriers total
    #pragma unroll
    for (int l = 0; l < TL; l++) {
        float s = v[l], q = v[l] * v[l];
        #pragma unroll
        for (int o = 16; o; o >>= 1) {
            s += __shfl_xor_sync(0xFFFFFFFFu, s, o);
            q += __shfl_xor_sync(0xFFFFFFFFu, q, o);
        }
        if (lane == 0) { wsum[l][wrp] = s; wsq[l][wrp] = q; }
    }
    __syncthreads();
    if (f < TL) {
        float S = 0.f, Q = 0.f;
        #pragma unroll
        for (int j = 0; j < 8; j++) { S += wsum[f][j]; Q += wsq[f][j]; }
        float mu  = S * (1.f / FF);
        float var = Q * (1.f / FF) - mu * mu;
        stats[f][0] = mu;
        stats[f][1] = rsqrtf(var + 1e-5f);
    }
    __syncthreads();

    const float gf = lng[f];
    const float bf = lnb[f];

    if (!FUSE_LIN) {
        #pragma unroll
        for (int l = 0; l < TL; l++) {
            float h = fmaxf((v[l] - stats[l][0]) * stats[l][1] * gf + bf, 0.f);
            out[((size_t)b * LL + l0 + l) * FF + f] = h;
        }
    } else {
        const float lwf = lw[f];
        const float lbv = lb[0];
        #pragma unroll
        for (int l = 0; l < TL; l++) {
            float h = fmaxf((v[l] - stats[l][0]) * stats[l][1] * gf + bf, 0.f);
            float p = h * lwf;
            #pragma unroll
            for (int o = 16; o; o >>= 1)
                p += __shfl_xor_sync(0xFFFFFFFFu, p, o);
            if (lane == 0) wsum[l][wrp] = p;
        }
        __syncthreads();
        if (f < TL) {
            float S = 0.f;
            #pragma unroll
            for (int j = 0; j < 8; j++) S += wsum[f][j];
            out[(size_t)b * LL + l0 + f] = fmaxf(S + lbv, 0.f);
        }
    }
}

// ---------------------------------------------------------------------------
extern "C" void kernel_launch(void* const* d_in, const int* in_sizes, int n_in,
                              void* d_out, int out_size) {
    const float* x    = (const float*)d_in[0];
    const int*   dur  = (const int*)  d_in[1];
    const float* c1w  = (const float*)d_in[3];
    const float* c1b  = (const float*)d_in[4];
    const float* ln1g = (const float*)d_in[5];
    const float* ln1b = (const float*)d_in[6];
    const float* c2w  = (const float*)d_in[7];
    const float* c2b  = (const float*)d_in[8];
    const float* ln2g = (const float*)d_in[9];
    const float* ln2b = (const float*)d_in[10];
    const float* lw   = (const float*)d_in[11];
    const float* lb   = (const float*)d_in[12];

    float* out = (float*)d_out;
    int M = (out_size - BB * LL) / (BB * DD);        // = 4096
    float* dur_pred = out + (size_t)BB * M * DD;

    float* h1;
    cudaGetSymbolAddress((void**)&h1, g_h1);

    cumsum_kernel<<<BB, LL>>>(dur);
    expand_kernel<<<dim3((M + 7) / 8, BB), 256>>>(x, out, M);

    conv_ln_kernel<false><<<dim3(LL / TL, BB), 256>>>(
        x, c1w, c1b, ln1g, ln1b, nullptr, nullptr, h1);
    conv_ln_kernel<true><<<dim3(LL / TL, BB), 256>>>(
        h1, c2w, c2b, ln2g, ln2b, lw, lb, dur_pred);
}

// round 5
// speedup vs baseline: 1.3825x; 1.0994x over previous
#include <cuda_runtime.h>
#include <cuda_bf16.h>
#include <cstdint>

#define BB 32
#define LL 512
#define DD 256
#define FF 256
#define TM 64                 // positions per CTA
#define A_ROWS 66             // TM + 2 halo
#define A_PITCH_B 528         // A row bytes: 256*2 + 16 pad (conflict-free ldmatrix)
#define B_PITCH_B 48          // B row bytes: 16*2 + 16 pad
#define NK 48                 // k16-steps: 3 taps * 16 d-chunks
#define NSTAGE 3
#define A_SPLIT_BYTES (A_ROWS * A_PITCH_B)        // 34848
#define B_SPLIT_BYTES (256 * B_PITCH_B)           // 12288
#define B_STAGE_BYTES (2 * B_SPLIT_BYTES)         // 24576
#define OFF_PAR 0
#define OFF_A 4096
#define OFF_B (OFF_A + 2 * A_SPLIT_BYTES)         // 73792
#define SMEM_TOTAL (OFF_B + NSTAGE * B_STAGE_BYTES)  // 147520
#define C_PITCH 260           // f32 elems, C overlays A region (64*260*4 = 66560)

// ---------------- global scratch (allocation-free rule) ----------------
__device__ __nv_bfloat16 g_x_hi[BB*LL*DD], g_x_lo[BB*LL*DD];
__device__ __nv_bfloat16 g_h_hi[BB*LL*FF], g_h_lo[BB*LL*FF];
__device__ __nv_bfloat16 g_w1_hi[3*FF*DD], g_w1_lo[3*FF*DD];
__device__ __nv_bfloat16 g_w2_hi[3*FF*DD], g_w2_lo[3*FF*DD];
__device__ int g_cs[BB*LL];

// ---------------- ptx helpers (all sm_80-baseline, no 'a' features) ----
__device__ __forceinline__ uint32_t smem_u32(const void* p) {
    uint32_t a;
    asm("{ .reg .u64 t; cvta.to.shared.u64 t, %1; cvt.u32.u64 %0, t; }"
        : "=r"(a) : "l"(p));
    return a;
}
__device__ __forceinline__ void cp16(uint32_t dst, const void* src) {
    asm volatile("cp.async.cg.shared.global [%0], [%1], 16;"
                 :: "r"(dst), "l"(src));
}
__device__ __forceinline__ void ldsm4(uint32_t r[4], uint32_t addr) {
    asm volatile("ldmatrix.sync.aligned.m8n8.x4.shared.b16 {%0,%1,%2,%3}, [%4];"
        : "=r"(r[0]), "=r"(r[1]), "=r"(r[2]), "=r"(r[3]) : "r"(addr));
}
__device__ __forceinline__ void mma16816(float c[4], const uint32_t a[4],
                                         uint32_t b0, uint32_t b1) {
    asm volatile(
        "mma.sync.aligned.m16n8k16.row.col.f32.bf16.bf16.f32 "
        "{%0,%1,%2,%3}, {%4,%5,%6,%7}, {%8,%9}, {%0,%1,%2,%3};"
        : "+f"(c[0]), "+f"(c[1]), "+f"(c[2]), "+f"(c[3])
        : "r"(a[0]), "r"(a[1]), "r"(a[2]), "r"(a[3]), "r"(b0), "r"(b1));
}

// ---------------- prep kernels ----------------
__global__ void split_x_kernel(const float* __restrict__ x,
                               __nv_bfloat16* __restrict__ hi,
                               __nv_bfloat16* __restrict__ lo, int n) {
    for (int i = blockIdx.x * blockDim.x + threadIdx.x; i < n;
         i += gridDim.x * blockDim.x) {
        float v = x[i];
        __nv_bfloat16 h = __float2bfloat16(v);
        hi[i] = h;
        lo[i] = __float2bfloat16(v - __bfloat162float(h));
    }
}
// w [k][d][f] (f contig) -> wt [k][f][d] split hi/lo
__global__ void split_w_kernel(const float* __restrict__ w,
                               __nv_bfloat16* __restrict__ hi,
                               __nv_bfloat16* __restrict__ lo) {
    int n = 3 * DD * FF;
    for (int i = blockIdx.x * blockDim.x + threadIdx.x; i < n;
         i += gridDim.x * blockDim.x) {
        int k = i / (FF * DD);
        int r = i % (FF * DD);
        int f = r / DD;
        int d = r % DD;
        float v = w[(k * DD + d) * FF + f];
        __nv_bfloat16 h = __float2bfloat16(v);
        hi[i] = h;
        lo[i] = __float2bfloat16(v - __bfloat162float(h));
    }
}

// ---------------- cumsum + expand (proven) ----------------
__global__ void cumsum_kernel(const int* __restrict__ dur) {
    __shared__ int s[LL];
    int t = threadIdx.x, b = blockIdx.x;
    s[t] = dur[b * LL + t];
    for (int off = 1; off < LL; off <<= 1) {
        __syncthreads();
        int v = (t >= off) ? s[t - off] : 0;
        __syncthreads();
        s[t] += v;
    }
    g_cs[b * LL + t] = s[t];
}

__global__ void expand_kernel(const float* __restrict__ x,
                              float* __restrict__ out, int M) {
    __shared__ int cs[LL];
    int b = blockIdx.y;
    for (int i = threadIdx.x; i < LL; i += blockDim.x) cs[i] = g_cs[b * LL + i];
    __syncthreads();

    int warp = threadIdx.x >> 5, lane = threadIdx.x & 31;
    int frame = blockIdx.x * 8 + warp;
    if (frame >= M) return;

    int total = cs[LL - 1];
    int lo = 0, hi = LL;
    while (lo < hi) {
        int mid = (lo + hi) >> 1;
        if (cs[mid] > frame) hi = mid; else lo = mid + 1;
    }
    int idx = lo < (LL - 1) ? lo : (LL - 1);
    bool valid = frame < total;

    const float4* src = reinterpret_cast<const float4*>(x + ((size_t)b * LL + idx) * DD);
    float4* dst = reinterpret_cast<float4*>(out + ((size_t)b * M + frame) * DD);
    float4 z = make_float4(0.f, 0.f, 0.f, 0.f);
    dst[lane]      = valid ? src[lane]      : z;
    dst[lane + 32] = valid ? src[lane + 32] : z;
}

// ---------------------------------------------------------------------------
// HMMA split-bf16 conv kernel.
//   C[m=64, f=256] = sum_{tap,d} x[l0+m+tap-1, d] * w'[tap][f][d]
// A in smem (66 rows x 256, hi+lo). B streamed by cp.async 3-stage pipeline.
// 8 warps = 2(m) x 4(n); warp tile m32 x n64. 3 MMA terms: hh, hl, lh.
// Epilogue: C->smem, per-row LayerNorm (+ReLU), conv1: re-split h to bf16
// hi/lo; conv2: fused linear head -> dur_pred.
// ---------------------------------------------------------------------------
template <bool FUSE_LIN>
__global__ void __launch_bounds__(256)
conv_mma_kernel(const __nv_bfloat16* __restrict__ in_hi,
                const __nv_bfloat16* __restrict__ in_lo,
                const __nv_bfloat16* __restrict__ w_hi,
                const __nv_bfloat16* __restrict__ w_lo,
                const float* __restrict__ bias,
                const float* __restrict__ lng, const float* __restrict__ lnb,
                const float* __restrict__ lw, const float* __restrict__ lb,
                __nv_bfloat16* __restrict__ out_hi,
                __nv_bfloat16* __restrict__ out_lo,
                float* __restrict__ dur_out) {
    extern __shared__ char smem[];
    const uint32_t sa = smem_u32(smem);
    const int tid  = threadIdx.x;
    const int lane = tid & 31;
    const int wid  = tid >> 5;
    const int wm   = wid & 1;          // m-warp (2)
    const int wn   = wid >> 1;         // n-warp (4)
    const int b    = blockIdx.x >> 3;
    const int l0   = (blockIdx.x & 7) * TM;

    // params -> smem
    float* bias_s = (float*)(smem + OFF_PAR);
    float* g_s    = (float*)(smem + OFF_PAR + 1024);
    float* bl_s   = (float*)(smem + OFF_PAR + 2048);
    float* lw_s   = (float*)(smem + OFF_PAR + 3072);
    bias_s[tid] = bias[tid];
    g_s[tid]    = lng[tid];
    bl_s[tid]   = lnb[tid];
    if (FUSE_LIN) lw_s[tid] = lw[tid];

    // ---- A load: 66 rows x 256 bf16, hi+lo, zero-padded halo ----
    {
        const uint4 z4 = make_uint4(0, 0, 0, 0);
        for (int u = tid; u < 2 * A_ROWS * 32; u += 256) {  // 32 x 16B per row
            int split = u / (A_ROWS * 32);
            int rem   = u % (A_ROWS * 32);
            int row   = rem >> 5;
            int p     = rem & 31;
            int l     = l0 + row - 1;
            bool valid = (l >= 0 && l < LL);
            const __nv_bfloat16* src = split ? in_lo : in_hi;
            uint4 v = valid
                ? *(const uint4*)(src + ((size_t)b * LL + l) * DD + p * 8)
                : z4;
            *(uint4*)(smem + OFF_A + split * A_SPLIT_BYTES + row * A_PITCH_B + p * 16) = v;
        }
    }

    // ---- B pipeline: stage kk = (tap = kk/16, dc = kk%16) ----
    auto issue_stage = [&](int kk, int buf) {
        int tap = kk >> 4, dc = kk & 15;
        uint32_t base = sa + OFF_B + buf * B_STAGE_BYTES;
        #pragma unroll
        for (int j = 0; j < 4; j++) {
            int u = tid + j * 256;                  // 1024 x 16B units
            int split = u >> 9;
            int rr    = (u >> 1) & 255;
            int half  = u & 1;
            const __nv_bfloat16* src = split ? w_lo : w_hi;
            cp16(base + split * B_SPLIT_BYTES + rr * B_PITCH_B + half * 16,
                 src + ((size_t)(tap * FF + rr) * DD + dc * 16 + half * 8));
        }
        asm volatile("cp.async.commit_group;" ::: "memory");
    };

    issue_stage(0, 0);
    issue_stage(1, 1);

    // ---- accumulators ----
    float cfr[2][8][4];
    #pragma unroll
    for (int mt = 0; mt < 2; mt++)
        #pragma unroll
        for (int j = 0; j < 8; j++)
            #pragma unroll
            for (int q = 0; q < 4; q++) cfr[mt][j][q] = 0.f;

    // invariant lane-address parts
    const uint32_t a_row_lane = (lane & 15);
    const uint32_t a_half     = (lane >> 4) * 16;
    const uint32_t b_row_lane = (lane & 7) + ((lane >> 4) & 1) * 8;
    const uint32_t b_half     = ((lane >> 3) & 1) * 16;

    for (int kk = 0; kk < NK; kk++) {
        if (kk + 2 < NK) { asm volatile("cp.async.wait_group 1;" ::: "memory"); }
        else             { asm volatile("cp.async.wait_group 0;" ::: "memory"); }
        __syncthreads();
        if (kk + 2 < NK) issue_stage(kk + 2, (kk + 2) % NSTAGE);

        const int tap = kk >> 4, dc = kk & 15;
        const uint32_t a_col = dc * 32 + a_half;
        const uint32_t bbase = sa + OFF_B + (kk % NSTAGE) * B_STAGE_BYTES;

        uint32_t ah[2][4], al[2][4];
        #pragma unroll
        for (int mt = 0; mt < 2; mt++) {
            uint32_t row = wm * 32 + mt * 16 + tap + a_row_lane;
            ldsm4(ah[mt], sa + OFF_A + row * A_PITCH_B + a_col);
            ldsm4(al[mt], sa + OFF_A + A_SPLIT_BYTES + row * A_PITCH_B + a_col);
        }
        uint32_t bh[4][4], bl[4][4];
        #pragma unroll
        for (int c = 0; c < 4; c++) {
            uint32_t row = wn * 64 + c * 16 + b_row_lane;
            ldsm4(bh[c], bbase + row * B_PITCH_B + b_half);
            ldsm4(bl[c], bbase + B_SPLIT_BYTES + row * B_PITCH_B + b_half);
        }

        // term sweeps (same-accum deps 16 apart): hh, hl, lh
        #pragma unroll
        for (int c = 0; c < 4; c++)
            #pragma unroll
            for (int mt = 0; mt < 2; mt++) {
                mma16816(cfr[mt][c * 2 + 0], ah[mt], bh[c][0], bh[c][1]);
                mma16816(cfr[mt][c * 2 + 1], ah[mt], bh[c][2], bh[c][3]);
            }
        #pragma unroll
        for (int c = 0; c < 4; c++)
            #pragma unroll
            for (int mt = 0; mt < 2; mt++) {
                mma16816(cfr[mt][c * 2 + 0], ah[mt], bl[c][0], bl[c][1]);
                mma16816(cfr[mt][c * 2 + 1], ah[mt], bl[c][2], bl[c][3]);
            }
        #pragma unroll
        for (int c = 0; c < 4; c++)
            #pragma unroll
            for (int mt = 0; mt < 2; mt++) {
                mma16816(cfr[mt][c * 2 + 0], al[mt], bh[c][0], bh[c][1]);
                mma16816(cfr[mt][c * 2 + 1], al[mt], bh[c][2], bh[c][3]);
            }
    }

    // ---- epilogue: C (+bias) -> smem overlaying A ----
    __syncthreads();
    float* Cs = (float*)(smem + OFF_A);
    {
        const int r0 = wm * 32 + (lane >> 2);
        #pragma unroll
        for (int mt = 0; mt < 2; mt++)
            #pragma unroll
            for (int j = 0; j < 8; j++) {
                int n = wn * 64 + j * 8 + (lane & 3) * 2;
                int rA = r0 + mt * 16;
                float b0 = bias_s[n], b1 = bias_s[n + 1];
                *(float2*)&Cs[rA * C_PITCH + n] =
                    make_float2(cfr[mt][j][0] + b0, cfr[mt][j][1] + b1);
                *(float2*)&Cs[(rA + 8) * C_PITCH + n] =
                    make_float2(cfr[mt][j][2] + b0, cfr[mt][j][3] + b1);
            }
    }
    __syncthreads();

    // ---- LayerNorm (+ReLU) per row: 4 threads per row ----
    {
        const int r = tid >> 2;          // 0..63
        const int q = tid & 3;           // quarter: 64 channels
        const float* crow = &Cs[r * C_PITCH + q * 64];
        float sum = 0.f, sq = 0.f;
        #pragma unroll
        for (int i = 0; i < 64; i++) {
            float v = crow[i];
            sum += v;
            sq  += v * v;
        }
        sum += __shfl_xor_sync(0xFFFFFFFFu, sum, 1);
        sq  += __shfl_xor_sync(0xFFFFFFFFu, sq, 1);
        sum += __shfl_xor_sync(0xFFFFFFFFu, sum, 2);
        sq  += __shfl_xor_sync(0xFFFFFFFFu, sq, 2);
        float mu   = sum * (1.f / FF);
        float rstd = rsqrtf(sq * (1.f / FF) - mu * mu + 1e-5f);

        const size_t row_g = (size_t)b * LL + l0 + r;
        if (!FUSE_LIN) {
            __nv_bfloat16* oh = out_hi + row_g * FF + q * 64;
            __nv_bfloat16* ol = out_lo + row_g * FF + q * 64;
            #pragma unroll
            for (int i = 0; i < 64; i++) {
                int f = q * 64 + i;
                float h = fmaxf((crow[i] - mu) * rstd * g_s[f] + bl_s[f], 0.f);
                __nv_bfloat16 hh = __float2bfloat16(h);
                oh[i] = hh;
                ol[i] = __float2bfloat16(h - __bfloat162float(hh));
            }
        } else {
            float dot = 0.f;
            #pragma unroll
            for (int i = 0; i < 64; i++) {
                int f = q * 64 + i;
                float h = fmaxf((crow[i] - mu) * rstd * g_s[f] + bl_s[f], 0.f);
                dot += h * lw_s[f];
            }
            dot += __shfl_xor_sync(0xFFFFFFFFu, dot, 1);
            dot += __shfl_xor_sync(0xFFFFFFFFu, dot, 2);
            if (q == 0) dur_out[row_g] = fmaxf(dot + lb[0], 0.f);
        }
    }
}

// ---------------------------------------------------------------------------
extern "C" void kernel_launch(void* const* d_in, const int* in_sizes, int n_in,
                              void* d_out, int out_size) {
    const float* x    = (const float*)d_in[0];
    const int*   dur  = (const int*)  d_in[1];
    const float* c1w  = (const float*)d_in[3];
    const float* c1b  = (const float*)d_in[4];
    const float* ln1g = (const float*)d_in[5];
    const float* ln1b = (const float*)d_in[6];
    const float* c2w  = (const float*)d_in[7];
    const float* c2b  = (const float*)d_in[8];
    const float* ln2g = (const float*)d_in[9];
    const float* ln2b = (const float*)d_in[10];
    const float* lw   = (const float*)d_in[11];
    const float* lb   = (const float*)d_in[12];

    float* out = (float*)d_out;
    int M = (out_size - BB * LL) / (BB * DD);   // 4096
    float* dur_pred = out + (size_t)BB * M * DD;

    __nv_bfloat16 *xh, *xl, *hh, *hl, *w1h, *w1l, *w2h, *w2l;
    cudaGetSymbolAddress((void**)&xh, g_x_hi);
    cudaGetSymbolAddress((void**)&xl, g_x_lo);
    cudaGetSymbolAddress((void**)&hh, g_h_hi);
    cudaGetSymbolAddress((void**)&hl, g_h_lo);
    cudaGetSymbolAddress((void**)&w1h, g_w1_hi);
    cudaGetSymbolAddress((void**)&w1l, g_w1_lo);
    cudaGetSymbolAddress((void**)&w2h, g_w2_hi);
    cudaGetSymbolAddress((void**)&w2l, g_w2_lo);

    cudaFuncSetAttribute(conv_mma_kernel<false>,
                         cudaFuncAttributeMaxDynamicSharedMemorySize, SMEM_TOTAL);
    cudaFuncSetAttribute(conv_mma_kernel<true>,
                         cudaFuncAttributeMaxDynamicSharedMemorySize, SMEM_TOTAL);

    // expand path
    cumsum_kernel<<<BB, LL>>>(dur);
    expand_kernel<<<dim3((M + 7) / 8, BB), 256>>>(x, out, M);

    // preps
    split_x_kernel<<<1024, 256>>>(x, xh, xl, BB * LL * DD);
    split_w_kernel<<<192, 256>>>(c1w, w1h, w1l);
    split_w_kernel<<<192, 256>>>(c2w, w2h, w2l);

    // predictor path: two HMMA convs
    conv_mma_kernel<false><<<BB * (LL / TM), 256, SMEM_TOTAL>>>(
        xh, xl, w1h, w1l, c1b, ln1g, ln1b, nullptr, nullptr, hh, hl, nullptr);
    conv_mma_kernel<true><<<BB * (LL / TM), 256, SMEM_TOTAL>>>(
        hh, hl, w2h, w2l, c2b, ln2g, ln2b, lw, lb, nullptr, nullptr, dur_pred);
}

// round 6
// speedup vs baseline: 1.5144x; 1.0954x over previous
#include <cuda_runtime.h>
#include <cuda_bf16.h>
#include <cstdint>

#define BB 32
#define LL 512
#define DD 256
#define FF 256
#define TM 64                 // positions per CTA
#define NTHR 512              // 16 warps: 2(m) x 8(n)
#define A_ROWS 66             // TM + 2 halo
#define A_PITCH_B 528         // A row bytes: 256*2 + 16 pad (conflict-free ldmatrix)
#define B_PITCH_B 48          // B row bytes: 16*2 + 16 pad
#define NK 48                 // k16-steps: 3 taps * 16 d-chunks
#define NSTAGE 3
#define A_SPLIT_BYTES (A_ROWS * A_PITCH_B)        // 34848
#define B_SPLIT_BYTES (256 * B_PITCH_B)           // 12288
#define B_STAGE_BYTES (2 * B_SPLIT_BYTES)         // 24576
#define OFF_PAR 0
#define OFF_A 4096
#define OFF_B (OFF_A + 2 * A_SPLIT_BYTES)         // 73792
#define SMEM_TOTAL (OFF_B + NSTAGE * B_STAGE_BYTES)  // 147520
#define C_PITCH 260           // f32 elems; C overlays A region (64*260*4 = 66560)

// ---------------- global scratch (allocation-free rule) ----------------
__device__ __nv_bfloat16 g_x_hi[BB*LL*DD], g_x_lo[BB*LL*DD];
__device__ __nv_bfloat16 g_h_hi[BB*LL*FF], g_h_lo[BB*LL*FF];
__device__ __nv_bfloat16 g_w1_hi[3*FF*DD], g_w1_lo[3*FF*DD];
__device__ __nv_bfloat16 g_w2_hi[3*FF*DD], g_w2_lo[3*FF*DD];
__device__ int g_cs[BB*LL];

// ---------------- ptx helpers (sm_80-baseline only) ----------------
__device__ __forceinline__ uint32_t smem_u32(const void* p) {
    uint32_t a;
    asm("{ .reg .u64 t; cvta.to.shared.u64 t, %1; cvt.u32.u64 %0, t; }"
        : "=r"(a) : "l"(p));
    return a;
}
__device__ __forceinline__ void cp16(uint32_t dst, const void* src) {
    asm volatile("cp.async.cg.shared.global [%0], [%1], 16;"
                 :: "r"(dst), "l"(src));
}
__device__ __forceinline__ void ldsm4(uint32_t r[4], uint32_t addr) {
    asm volatile("ldmatrix.sync.aligned.m8n8.x4.shared.b16 {%0,%1,%2,%3}, [%4];"
        : "=r"(r[0]), "=r"(r[1]), "=r"(r[2]), "=r"(r[3]) : "r"(addr));
}
__device__ __forceinline__ void mma16816(float c[4], const uint32_t a[4],
                                         uint32_t b0, uint32_t b1) {
    asm volatile(
        "mma.sync.aligned.m16n8k16.row.col.f32.bf16.bf16.f32 "
        "{%0,%1,%2,%3}, {%4,%5,%6,%7}, {%8,%9}, {%0,%1,%2,%3};"
        : "+f"(c[0]), "+f"(c[1]), "+f"(c[2]), "+f"(c[3])
        : "r"(a[0]), "r"(a[1]), "r"(a[2]), "r"(a[3]), "r"(b0), "r"(b1));
}

// ---------------- prep kernels ----------------
__global__ void split_x_kernel(const float* __restrict__ x,
                               __nv_bfloat16* __restrict__ hi,
                               __nv_bfloat16* __restrict__ lo, int n) {
    for (int i = blockIdx.x * blockDim.x + threadIdx.x; i < n;
         i += gridDim.x * blockDim.x) {
        float v = x[i];
        __nv_bfloat16 h = __float2bfloat16(v);
        hi[i] = h;
        lo[i] = __float2bfloat16(v - __bfloat162float(h));
    }
}
// w [k][d][f] -> wt [k][f][d], split hi/lo, via 32x32 smem tile transpose
__global__ void split_w_kernel(const float* __restrict__ w,
                               __nv_bfloat16* __restrict__ hi,
                               __nv_bfloat16* __restrict__ lo) {
    __shared__ float tile[32][33];
    int k  = blockIdx.z;
    int d0 = blockIdx.x * 32;
    int f0 = blockIdx.y * 32;
    int tx = threadIdx.x, ty = threadIdx.y;      // 32 x 8
    #pragma unroll
    for (int i = 0; i < 4; i++) {
        int d = d0 + ty + i * 8;
        tile[ty + i * 8][tx] = w[((size_t)k * DD + d) * FF + f0 + tx];
    }
    __syncthreads();
    #pragma unroll
    for (int i = 0; i < 4; i++) {
        int f = f0 + ty + i * 8;
        float v = tile[tx][ty + i * 8];
        __nv_bfloat16 h = __float2bfloat16(v);
        size_t o = ((size_t)k * FF + f) * DD + d0 + tx;
        hi[o] = h;
        lo[o] = __float2bfloat16(v - __bfloat162float(h));
    }
}

// ---------------- cumsum + expand (proven) ----------------
__global__ void cumsum_kernel(const int* __restrict__ dur) {
    __shared__ int s[LL];
    int t = threadIdx.x, b = blockIdx.x;
    s[t] = dur[b * LL + t];
    for (int off = 1; off < LL; off <<= 1) {
        __syncthreads();
        int v = (t >= off) ? s[t - off] : 0;
        __syncthreads();
        s[t] += v;
    }
    g_cs[b * LL + t] = s[t];
}

__global__ void expand_kernel(const float* __restrict__ x,
                              float* __restrict__ out, int M) {
    __shared__ int cs[LL];
    int b = blockIdx.y;
    for (int i = threadIdx.x; i < LL; i += blockDim.x) cs[i] = g_cs[b * LL + i];
    __syncthreads();

    int warp = threadIdx.x >> 5, lane = threadIdx.x & 31;
    int frame = blockIdx.x * 8 + warp;
    if (frame >= M) return;

    int total = cs[LL - 1];
    int lo = 0, hi = LL;
    while (lo < hi) {
        int mid = (lo + hi) >> 1;
        if (cs[mid] > frame) hi = mid; else lo = mid + 1;
    }
    int idx = lo < (LL - 1) ? lo : (LL - 1);
    bool valid = frame < total;

    const float4* src = reinterpret_cast<const float4*>(x + ((size_t)b * LL + idx) * DD);
    float4* dst = reinterpret_cast<float4*>(out + ((size_t)b * M + frame) * DD);
    float4 z = make_float4(0.f, 0.f, 0.f, 0.f);
    dst[lane]      = valid ? src[lane]      : z;
    dst[lane + 32] = valid ? src[lane + 32] : z;
}

// ---------------------------------------------------------------------------
// HMMA split-bf16 conv kernel, 512 threads / 16 warps (2m x 8n),
// warp tile m32 x n32. Same memory layout & fragment maps as R5.
// ---------------------------------------------------------------------------
template <bool FUSE_LIN>
__global__ void __launch_bounds__(NTHR)
conv_mma_kernel(const __nv_bfloat16* __restrict__ in_hi,
                const __nv_bfloat16* __restrict__ in_lo,
                const __nv_bfloat16* __restrict__ w_hi,
                const __nv_bfloat16* __restrict__ w_lo,
                const float* __restrict__ bias,
                const float* __restrict__ lng, const float* __restrict__ lnb,
                const float* __restrict__ lw, const float* __restrict__ lb,
                __nv_bfloat16* __restrict__ out_hi,
                __nv_bfloat16* __restrict__ out_lo,
                float* __restrict__ dur_out) {
    extern __shared__ char smem[];
    const uint32_t sa = smem_u32(smem);
    const int tid  = threadIdx.x;
    const int lane = tid & 31;
    const int wid  = tid >> 5;
    const int wm   = wid & 1;          // m-warp (2) -> m32
    const int wn   = wid >> 1;         // n-warp (8) -> n32
    const int b    = blockIdx.x >> 3;
    const int l0   = (blockIdx.x & 7) * TM;

    // params -> smem
    float* bias_s = (float*)(smem + OFF_PAR);
    float* g_s    = (float*)(smem + OFF_PAR + 1024);
    float* bl_s   = (float*)(smem + OFF_PAR + 2048);
    float* lw_s   = (float*)(smem + OFF_PAR + 3072);
    if (tid < FF) {
        bias_s[tid] = bias[tid];
        g_s[tid]    = lng[tid];
        bl_s[tid]   = lnb[tid];
        if (FUSE_LIN) lw_s[tid] = lw[tid];
    }

    // ---- A load: 66 rows x 256 bf16, hi+lo, zero-padded halo ----
    {
        const uint4 z4 = make_uint4(0, 0, 0, 0);
        for (int u = tid; u < 2 * A_ROWS * 32; u += NTHR) {
            int split = u / (A_ROWS * 32);
            int rem   = u % (A_ROWS * 32);
            int row   = rem >> 5;
            int p     = rem & 31;
            int l     = l0 + row - 1;
            bool valid = (l >= 0 && l < LL);
            const __nv_bfloat16* src = split ? in_lo : in_hi;
            uint4 v = valid
                ? *(const uint4*)(src + ((size_t)b * LL + l) * DD + p * 8)
                : z4;
            *(uint4*)(smem + OFF_A + split * A_SPLIT_BYTES + row * A_PITCH_B + p * 16) = v;
        }
    }

    // ---- B pipeline: stage kk = (tap = kk/16, dc = kk%16) ----
    auto issue_stage = [&](int kk, int buf) {
        int tap = kk >> 4, dc = kk & 15;
        uint32_t base = sa + OFF_B + buf * B_STAGE_BYTES;
        #pragma unroll
        for (int j = 0; j < 2; j++) {
            int u = tid + j * NTHR;                 // 1024 x 16B units
            int split = u >> 9;
            int rr    = (u >> 1) & 255;
            int half  = u & 1;
            const __nv_bfloat16* src = split ? w_lo : w_hi;
            cp16(base + split * B_SPLIT_BYTES + rr * B_PITCH_B + half * 16,
                 src + ((size_t)(tap * FF + rr) * DD + dc * 16 + half * 8));
        }
        asm volatile("cp.async.commit_group;" ::: "memory");
    };

    issue_stage(0, 0);
    issue_stage(1, 1);

    // ---- accumulators: [mt][j = c*2+half][4] ----
    float cfr[2][4][4];
    #pragma unroll
    for (int mt = 0; mt < 2; mt++)
        #pragma unroll
        for (int j = 0; j < 4; j++)
            #pragma unroll
            for (int q = 0; q < 4; q++) cfr[mt][j][q] = 0.f;

    const uint32_t a_row_lane = (lane & 15);
    const uint32_t a_half     = (lane >> 4) * 16;
    const uint32_t b_row_lane = (lane & 7) + ((lane >> 4) & 1) * 8;
    const uint32_t b_half     = ((lane >> 3) & 1) * 16;

    for (int kk = 0; kk < NK; kk++) {
        if (kk + 2 < NK) { asm volatile("cp.async.wait_group 1;" ::: "memory"); }
        else             { asm volatile("cp.async.wait_group 0;" ::: "memory"); }
        __syncthreads();
        if (kk + 2 < NK) issue_stage(kk + 2, (kk + 2) % NSTAGE);

        const int tap = kk >> 4, dc = kk & 15;
        const uint32_t a_col = dc * 32 + a_half;
        const uint32_t bbase = sa + OFF_B + (kk % NSTAGE) * B_STAGE_BYTES;

        uint32_t ah[2][4], al[2][4];
        #pragma unroll
        for (int mt = 0; mt < 2; mt++) {
            uint32_t row = wm * 32 + mt * 16 + tap + a_row_lane;
            ldsm4(ah[mt], sa + OFF_A + row * A_PITCH_B + a_col);
            ldsm4(al[mt], sa + OFF_A + A_SPLIT_BYTES + row * A_PITCH_B + a_col);
        }
        uint32_t bh[2][4], bl[2][4];
        #pragma unroll
        for (int c = 0; c < 2; c++) {
            uint32_t row = wn * 32 + c * 16 + b_row_lane;
            ldsm4(bh[c], bbase + row * B_PITCH_B + b_half);
            ldsm4(bl[c], bbase + B_SPLIT_BYTES + row * B_PITCH_B + b_half);
        }

        // three split terms: hh, hl, lh
        #pragma unroll
        for (int c = 0; c < 2; c++)
            #pragma unroll
            for (int mt = 0; mt < 2; mt++) {
                mma16816(cfr[mt][c * 2 + 0], ah[mt], bh[c][0], bh[c][1]);
                mma16816(cfr[mt][c * 2 + 1], ah[mt], bh[c][2], bh[c][3]);
            }
        #pragma unroll
        for (int c = 0; c < 2; c++)
            #pragma unroll
            for (int mt = 0; mt < 2; mt++) {
                mma16816(cfr[mt][c * 2 + 0], ah[mt], bl[c][0], bl[c][1]);
                mma16816(cfr[mt][c * 2 + 1], ah[mt], bl[c][2], bl[c][3]);
            }
        #pragma unroll
        for (int c = 0; c < 2; c++)
            #pragma unroll
            for (int mt = 0; mt < 2; mt++) {
                mma16816(cfr[mt][c * 2 + 0], al[mt], bh[c][0], bh[c][1]);
                mma16816(cfr[mt][c * 2 + 1], al[mt], bh[c][2], bh[c][3]);
            }
    }

    // ---- epilogue: C (+bias) -> smem overlaying A ----
    __syncthreads();
    float* Cs = (float*)(smem + OFF_A);
    {
        const int r0 = wm * 32 + (lane >> 2);
        #pragma unroll
        for (int mt = 0; mt < 2; mt++)
            #pragma unroll
            for (int j = 0; j < 4; j++) {
                int n = wn * 32 + j * 8 + (lane & 3) * 2;
                int rA = r0 + mt * 16;
                float b0 = bias_s[n], b1 = bias_s[n + 1];
                *(float2*)&Cs[rA * C_PITCH + n] =
                    make_float2(cfr[mt][j][0] + b0, cfr[mt][j][1] + b1);
                *(float2*)&Cs[(rA + 8) * C_PITCH + n] =
                    make_float2(cfr[mt][j][2] + b0, cfr[mt][j][3] + b1);
            }
    }
    __syncthreads();

    // ---- LayerNorm (+ReLU) per row: 8 threads per row, 32 channels each ----
    {
        const int r = tid >> 3;          // 0..63
        const int q = tid & 7;           // eighth: 32 channels
        const float* crow = &Cs[r * C_PITCH + q * 32];
        float sum = 0.f, sq = 0.f;
        #pragma unroll
        for (int i = 0; i < 32; i++) {
            float v = crow[i];
            sum += v;
            sq  += v * v;
        }
        #pragma unroll
        for (int o = 1; o < 8; o <<= 1) {
            sum += __shfl_xor_sync(0xFFFFFFFFu, sum, o);
            sq  += __shfl_xor_sync(0xFFFFFFFFu, sq, o);
        }
        float mu   = sum * (1.f / FF);
        float rstd = rsqrtf(sq * (1.f / FF) - mu * mu + 1e-5f);

        const size_t row_g = (size_t)b * LL + l0 + r;
        if (!FUSE_LIN) {
            __nv_bfloat16* oh = out_hi + row_g * FF + q * 32;
            __nv_bfloat16* ol = out_lo + row_g * FF + q * 32;
            #pragma unroll
            for (int i = 0; i < 32; i++) {
                int f = q * 32 + i;
                float h = fmaxf((crow[i] - mu) * rstd * g_s[f] + bl_s[f], 0.f);
                __nv_bfloat16 hh = __float2bfloat16(h);
                oh[i] = hh;
                ol[i] = __float2bfloat16(h - __bfloat162float(hh));
            }
        } else {
            float dot = 0.f;
            #pragma unroll
            for (int i = 0; i < 32; i++) {
                int f = q * 32 + i;
                float h = fmaxf((crow[i] - mu) * rstd * g_s[f] + bl_s[f], 0.f);
                dot += h * lw_s[f];
            }
            #pragma unroll
            for (int o = 1; o < 8; o <<= 1)
                dot += __shfl_xor_sync(0xFFFFFFFFu, dot, o);
            if (q == 0) dur_out[row_g] = fmaxf(dot + lb[0], 0.f);
        }
    }
}

// ---------------------------------------------------------------------------
extern "C" void kernel_launch(void* const* d_in, const int* in_sizes, int n_in,
                              void* d_out, int out_size) {
    const float* x    = (const float*)d_in[0];
    const int*   dur  = (const int*)  d_in[1];
    const float* c1w  = (const float*)d_in[3];
    const float* c1b  = (const float*)d_in[4];
    const float* ln1g = (const float*)d_in[5];
    const float* ln1b = (const float*)d_in[6];
    const float* c2w  = (const float*)d_in[7];
    const float* c2b  = (const float*)d_in[8];
    const float* ln2g = (const float*)d_in[9];
    const float* ln2b = (const float*)d_in[10];
    const float* lw   = (const float*)d_in[11];
    const float* lb   = (const float*)d_in[12];

    float* out = (float*)d_out;
    int M = (out_size - BB * LL) / (BB * DD);   // 4096
    float* dur_pred = out + (size_t)BB * M * DD;

    __nv_bfloat16 *xh, *xl, *hh, *hl, *w1h, *w1l, *w2h, *w2l;
    cudaGetSymbolAddress((void**)&xh, g_x_hi);
    cudaGetSymbolAddress((void**)&xl, g_x_lo);
    cudaGetSymbolAddress((void**)&hh, g_h_hi);
    cudaGetSymbolAddress((void**)&hl, g_h_lo);
    cudaGetSymbolAddress((void**)&w1h, g_w1_hi);
    cudaGetSymbolAddress((void**)&w1l, g_w1_lo);
    cudaGetSymbolAddress((void**)&w2h, g_w2_hi);
    cudaGetSymbolAddress((void**)&w2l, g_w2_lo);

    cudaFuncSetAttribute(conv_mma_kernel<false>,
                         cudaFuncAttributeMaxDynamicSharedMemorySize, SMEM_TOTAL);
    cudaFuncSetAttribute(conv_mma_kernel<true>,
                         cudaFuncAttributeMaxDynamicSharedMemorySize, SMEM_TOTAL);

    // expand path
    cumsum_kernel<<<BB, LL>>>(dur);
    expand_kernel<<<dim3((M + 7) / 8, BB), 256>>>(x, out, M);

    // preps
    split_x_kernel<<<1024, 256>>>(x, xh, xl, BB * LL * DD);
    split_w_kernel<<<dim3(8, 8, 3), dim3(32, 8)>>>(c1w, w1h, w1l);
    split_w_kernel<<<dim3(8, 8, 3), dim3(32, 8)>>>(c2w, w2h, w2l);

    // predictor path: two HMMA convs
    conv_mma_kernel<false><<<BB * (LL / TM), NTHR, SMEM_TOTAL>>>(
        xh, xl, w1h, w1l, c1b, ln1g, ln1b, nullptr, nullptr, hh, hl, nullptr);
    conv_mma_kernel<true><<<BB * (LL / TM), NTHR, SMEM_TOTAL>>>(
        hh, hl, w2h, w2l, c2b, ln2g, ln2b, lw, lb, nullptr, nullptr, dur_pred);
}